// round 14
// baseline (speedup 1.0000x reference)
#include <cuda_runtime.h>
#include <cstdint>

#define B_   256
#define T_   100
#define NIN  700
#define KP   704            // NIN padded to multiple of 16
#define NN   2068
#define NNP  2176           // row stride (multiple of 64)
#define NOUT 20
#define TAU  0.6f
#define KC   320            // Eigen kc panel size
#define NSEG 7              // ceil(2068/320)
#define MROWS (B_ * T_)     // 25600

// GEMM tiling (combined kernel, 512-thread CTA, micro 4x4)
#define BM 128
#define BN 64
#define BK 16
#define NKT   (KP / BK)     // 44 k-tiles; panel folds before tiles 20 and 40
#define NCOLB 33            // col blocks (cols 0..2111 cover NN)
#define TPT   (2 * NCOLB)   // 66 tiles per timestep (256 rows = 2 row-blocks)
#define NTILES (200 * NCOLB) // 6600
#define NGEMM 148           // persistent GEMM CTAs
#define NSTEP 128           // steps CTAs (2 batches each)

#define NT    512
#define W4ROW 517           // 2068/4 float4s per W_rec row

// ---------------- scratch (device globals; no runtime allocation) ----------
__device__ float g_ff[(size_t)MROWS * NNP];      // folded ff = (p0+p1)+p2
__device__ float g_xp[(size_t)MROWS * KP];       // x staged [r=t*B+b][k], zero-padded
__device__ float g_w1t[(size_t)KP * NNP];        // W_fc1^T zero-padded [k][n]
__device__ unsigned g_next;                      // tile steal counter
__device__ unsigned g_done[T_];                  // per-timestep completed tiles

// ---------------- staging ---------------------------------------------------
__global__ void zero_ctrl_kernel() {
    int i = threadIdx.x;
    if (i < T_) g_done[i] = 0u;
    if (i == T_) g_next = 0u;
}

__global__ void pad_x_kernel(const float* __restrict__ x) {
    size_t idx = (size_t)blockIdx.x * blockDim.x + threadIdx.x;
    if (idx < (size_t)MROWS * KP) {
        int r = (int)(idx / KP);
        int k = (int)(idx - (size_t)r * KP);
        int t = r >> 8;                 // r = t*256 + b
        int b = r & 255;
        g_xp[idx] = (k < NIN) ? x[((size_t)b * T_ + t) * NIN + k] : 0.0f;
    }
}

__global__ void pad_w1t_kernel(const float* __restrict__ W1) {
    size_t idx = (size_t)blockIdx.x * blockDim.x + threadIdx.x;
    if (idx < (size_t)KP * NNP) {
        int k = (int)(idx / NNP);
        int n = (int)(idx - (size_t)k * NNP);
        g_w1t[idx] = (k < NIN && n < NN) ? W1[(size_t)n * NIN + k] : 0.0f;
    }
}

// ---------------- shared memory union ----------------------------------------
union SMem {
    struct {
        float As[2][BK][BM];    // 16 KB
        float Bs[2][BK][BN];    // 8 KB
        unsigned tile;
    } g;
    struct {
        int list[NN];           // ~8.3 KB
        int wcnt[16];
        int tcnt;
        int seg[NSEG];
        unsigned ready;
    } s;
};

__device__ __forceinline__ float4 f4add(float4 a, float4 b) {
    return make_float4(__fadd_rn(a.x, b.x), __fadd_rn(a.y, b.y),
                       __fadd_rn(a.z, b.z), __fadd_rn(a.w, b.w));
}

// ---------------- one GEMM tile (512 threads, micro 4x4, panel fold) ---------
// Per output element (Eigen-exact): pac = seq-FMA over kc=320 panel;
// tot = fadd(tot, pac) at panel boundaries (k=320, 640) and at the end.
__device__ __forceinline__ void do_tile(unsigned n, SMem* sm, int tid) {
    int rowblk = (int)(n / NCOLB);
    int colblk = (int)(n % NCOLB);
    int row0 = rowblk * BM;
    int col0 = colblk * BN;
    unsigned tt = (unsigned)(rowblk >> 1);

    int arow = tid >> 2;                 // 0..127
    int asub = (tid & 3) * 4;            // 0,4,8,12
    const float* ap = g_xp + (size_t)(row0 + arow) * KP + asub;

    int bk  = tid >> 5;                  // 0..15
    int bn2 = (tid & 31) * 2;            // 0..62
    const float* bp = g_w1t + (size_t)bk * NNP + (col0 + bn2);

    int tr = (tid >> 4) * 4;             // 0..124
    int tc = (tid & 15) * 4;             // 0..60

    float4 ra;
    float2 rb;

    // prolog: tile 0
    ra = *(const float4*)(ap);
    rb = *(const float2*)(bp);
    sm->g.As[0][asub + 0][arow] = ra.x; sm->g.As[0][asub + 1][arow] = ra.y;
    sm->g.As[0][asub + 2][arow] = ra.z; sm->g.As[0][asub + 3][arow] = ra.w;
    *(float2*)&sm->g.Bs[0][bk][bn2] = rb;
    __syncthreads();

    float tot[4][4], pac[4][4];
    #pragma unroll
    for (int i = 0; i < 4; i++)
        #pragma unroll
        for (int j = 0; j < 4; j++) { tot[i][j] = 0.0f; pac[i][j] = 0.0f; }

    for (int tI = 0; tI < NKT; tI++) {
        if (tI == 20 || tI == 40) {                 // panel boundary fold
            #pragma unroll
            for (int i = 0; i < 4; i++)
                #pragma unroll
                for (int j = 0; j < 4; j++) {
                    tot[i][j] = __fadd_rn(tot[i][j], pac[i][j]);
                    pac[i][j] = 0.0f;
                }
        }

        int  buf  = tI & 1;
        bool more = (tI + 1 < NKT);

        if (more) {
            ra = *(const float4*)(ap + (tI + 1) * BK);
            rb = *(const float2*)(bp + (size_t)(tI + 1) * BK * NNP);
        }

        #pragma unroll
        for (int kk = 0; kk < BK; kk++) {
            float4 av = *(const float4*)&sm->g.As[buf][kk][tr];
            float4 bv = *(const float4*)&sm->g.Bs[buf][kk][tc];
            float a[4] = { av.x, av.y, av.z, av.w };
            float bb[4] = { bv.x, bv.y, bv.z, bv.w };
            #pragma unroll
            for (int i = 0; i < 4; i++)
                #pragma unroll
                for (int j = 0; j < 4; j++)
                    pac[i][j] = __fmaf_rn(a[i], bb[j], pac[i][j]);
        }

        if (more) {
            int nb = buf ^ 1;
            sm->g.As[nb][asub + 0][arow] = ra.x; sm->g.As[nb][asub + 1][arow] = ra.y;
            sm->g.As[nb][asub + 2][arow] = ra.z; sm->g.As[nb][asub + 3][arow] = ra.w;
            *(float2*)&sm->g.Bs[nb][bk][bn2] = rb;
        }
        __syncthreads();
    }

    #pragma unroll
    for (int i = 0; i < 4; i++) {
        #pragma unroll
        for (int j = 0; j < 4; j++)
            tot[i][j] = __fadd_rn(tot[i][j], pac[i][j]);   // final panel fold
        *(float4*)(g_ff + (size_t)(row0 + tr + i) * NNP + (col0 + tc)) = *(float4*)&tot[i][0];
    }

    __threadfence();          // release C stores
    __syncthreads();          // all threads fenced
    if (tid == 0) atomicAdd(&g_done[tt], 1u);
}

// ---------------- fused kernel: per-CTA role split ---------------------------
__global__ __launch_bounds__(NT, 2) void fused_kernel(const float* __restrict__ Wrec,
                                                      float* __restrict__ out) {
    __shared__ SMem sm;

    int bid = blockIdx.x;
    int tid = threadIdx.x;

    if (bid < NGEMM) {
        // ---- GEMM role: persistent tile drainer ----
        for (;;) {
            if (tid == 0) sm.g.tile = atomicAdd(&g_next, 1u);
            __syncthreads();
            unsigned n = sm.g.tile;
            __syncthreads();
            if (n >= NTILES) return;
            do_tile(n, &sm, tid);
        }
    }

    // ---- steps role: 2 batches per CTA ----
    int sbi  = bid - NGEMM;              // 0..127
    int wid  = tid >> 5;
    int lane = tid & 31;
    unsigned ltmask = (1u << lane) - 1u;
    bool tv  = (tid < NOUT);

    const float4* W4 = (const float4*)Wrec;

    float4 mv[2], sv[2];
    float  mt[2], st[2];
    #pragma unroll
    for (int bb = 0; bb < 2; bb++) {
        mv[bb] = make_float4(0.f, 0.f, 0.f, 0.f);
        sv[bb] = make_float4(0.f, 0.f, 0.f, 0.f);
        mt[bb] = 0.f; st[bb] = 0.f;
    }

    for (int t = 0; t < T_; t++) {
        // ---- wait for ff[t] (poll per-t tile counter) ----
        for (;;) {
            if (tid == 0)
                sm.s.ready = (*(volatile unsigned*)&g_done[t] >= TPT) ? 1u : 0u;
            __syncthreads();
            unsigned rd = sm.s.ready;
            __syncthreads();
            if (rd) break;
            __nanosleep(256);
        }
        __threadfence();   // acquire: order ff reads after observed completion

        #pragma unroll 1
        for (int bb = 0; bb < 2; bb++) {
            int b = 2 * sbi + bb;

            // ---- ff load (already panel-folded by GEMM) ----
            size_t rbase = ((size_t)t * B_ + b) * NNP;
            float4 ffv = ((const float4*)g_ff)[(rbase >> 2) + tid];
            float  fft = tv ? g_ff[rbase + 2048 + tid] : 0.f;

            // ---- compaction: 4-bit mask + warp scan + cross-warp prefix ----
            float4 svb = sv[bb];
            unsigned am = (svb.x != 0.f ? 1u : 0u) | (svb.y != 0.f ? 2u : 0u)
                        | (svb.z != 0.f ? 4u : 0u) | (svb.w != 0.f ? 8u : 0u);
            int nact = __popc(am);
            int scan = nact;
            #pragma unroll
            for (int d = 1; d < 32; d <<= 1) {
                int o = __shfl_up_sync(0xffffffffu, scan, d);
                if (lane >= d) scan += o;
            }
            if (lane == 31) sm.s.wcnt[wid] = scan;

            bool ta = tv && (st[bb] != 0.f);
            unsigned tmask = __ballot_sync(0xffffffffu, ta);   // valid in warp 0
            if (tid == 0) sm.s.tcnt = __popc(tmask);
            __syncthreads();

            int vbase = 0, vtotal = 0;
            #pragma unroll
            for (int w = 0; w < 16; w++) {
                int c = sm.s.wcnt[w];
                if (w < wid) vbase += c;
                vtotal += c;
            }
            int pos = vbase + (scan - nact);
            if (am & 1u) sm.s.list[pos++] = 4 * tid + 0;
            if (am & 2u) sm.s.list[pos++] = 4 * tid + 1;
            if (am & 4u) sm.s.list[pos++] = 4 * tid + 2;
            if (am & 8u) sm.s.list[pos++] = 4 * tid + 3;
            if (ta) sm.s.list[vtotal + __popc(tmask & ltmask)] = 2048 + tid;
            __syncthreads();

            int cnt = vtotal + sm.s.tcnt;

            // ---- segment boundaries: lower_bound of (p+1)*320 ----
            if (tid < NSEG) {
                int target = (tid + 1) * KC;
                int lo = 0, hi = cnt;
                while (lo < hi) {
                    int mid = (lo + hi) >> 1;
                    if (sm.s.list[mid] < target) lo = mid + 1; else hi = mid;
                }
                sm.s.seg[tid] = lo;
            }
            __syncthreads();

            // ---- rec: per-segment plain adds, fold between segments ----
            float4 rec  = make_float4(0.f, 0.f, 0.f, 0.f);
            float  rect = 0.f;

            int start = 0;
            #pragma unroll 1
            for (int p = 0; p < NSEG; p++) {
                int end = sm.s.seg[p];
                float4 part = make_float4(0.f, 0.f, 0.f, 0.f);
                float  partt = 0.f;
                int i = start;
                for (; i + 4 <= end; i += 4) {
                    int m0 = sm.s.list[i + 0], m1 = sm.s.list[i + 1];
                    int m2 = sm.s.list[i + 2], m3 = sm.s.list[i + 3];
                    float4 v0 = W4[(size_t)m0 * W4ROW + tid];
                    float4 v1 = W4[(size_t)m1 * W4ROW + tid];
                    float4 v2 = W4[(size_t)m2 * W4ROW + tid];
                    float4 v3 = W4[(size_t)m3 * W4ROW + tid];
                    float  u0 = tv ? Wrec[(size_t)m0 * NN + 2048 + tid] : 0.f;
                    float  u1 = tv ? Wrec[(size_t)m1 * NN + 2048 + tid] : 0.f;
                    float  u2 = tv ? Wrec[(size_t)m2 * NN + 2048 + tid] : 0.f;
                    float  u3 = tv ? Wrec[(size_t)m3 * NN + 2048 + tid] : 0.f;
                    part = f4add(part, v0); partt = __fadd_rn(partt, u0);
                    part = f4add(part, v1); partt = __fadd_rn(partt, u1);
                    part = f4add(part, v2); partt = __fadd_rn(partt, u2);
                    part = f4add(part, v3); partt = __fadd_rn(partt, u3);
                }
                for (; i < end; i++) {
                    int mr = sm.s.list[i];
                    float4 v0 = W4[(size_t)mr * W4ROW + tid];
                    float  u0 = tv ? Wrec[(size_t)mr * NN + 2048 + tid] : 0.f;
                    part = f4add(part, v0); partt = __fadd_rn(partt, u0);
                }
                rec  = f4add(rec, part);        // fadd(x,+0) == x for empty segs
                rect = __fadd_rn(rect, partt);
                start = end;
            }

            // ---- membrane update + spikes (unfused, reference order) ----
            {
                float4 cur = f4add(ffv, rec);
                mv[bb] = make_float4(
                    __fadd_rn(__fmul_rn(__fmul_rn(TAU, mv[bb].x), __fsub_rn(1.f, svb.x)), cur.x),
                    __fadd_rn(__fmul_rn(__fmul_rn(TAU, mv[bb].y), __fsub_rn(1.f, svb.y)), cur.y),
                    __fadd_rn(__fmul_rn(__fmul_rn(TAU, mv[bb].z), __fsub_rn(1.f, svb.z)), cur.z),
                    __fadd_rn(__fmul_rn(__fmul_rn(TAU, mv[bb].w), __fsub_rn(1.f, svb.w)), cur.w));
                sv[bb] = make_float4(mv[bb].x >= 1.f ? 1.f : 0.f, mv[bb].y >= 1.f ? 1.f : 0.f,
                                     mv[bb].z >= 1.f ? 1.f : 0.f, mv[bb].w >= 1.f ? 1.f : 0.f);
            }
            if (tv) {
                float cur = __fadd_rn(fft, rect);
                mt[bb] = __fadd_rn(__fmul_rn(__fmul_rn(TAU, mt[bb]), __fsub_rn(1.f, st[bb])), cur);
                st[bb] = (mt[bb] >= 1.f) ? 1.f : 0.f;
                out[((size_t)b * T_ + t) * NOUT + tid] = st[bb];
            }

            __syncthreads();   // protect shared reuse (next batch / next step)
        }
    }
}

// ---------------- launch -----------------------------------------------------
extern "C" void kernel_launch(void* const* d_in, const int* in_sizes, int n_in,
                              void* d_out, int out_size) {
    const float* x  = (const float*)d_in[0];   // [B, T, NIN]
    const float* W1 = (const float*)d_in[1];   // [NN, NIN]
    const float* Wr = (const float*)d_in[2];   // [NN, NN]
    float* out = (float*)d_out;                // [B, T, NOUT]

    zero_ctrl_kernel<<<1, 128>>>();
    {
        size_t n = (size_t)MROWS * KP;
        pad_x_kernel<<<(unsigned)((n + 255) / 256), 256>>>(x);
    }
    {
        size_t n = (size_t)KP * NNP;
        pad_w1t_kernel<<<(unsigned)((n + 255) / 256), 256>>>(W1);
    }

    fused_kernel<<<NGEMM + NSTEP, NT>>>(Wr, out);
}

// round 15
// speedup vs baseline: 1.2961x; 1.2961x over previous
#include <cuda_runtime.h>
#include <cstdint>

#define B_   256
#define T_   100
#define NIN  700
#define KP   704            // NIN padded to multiple of 16
#define NN   2068
#define NNP  2176           // row stride (multiple of 64); 544 float4s
#define NCOLB 33            // col blocks computed (cols 0..2111 >= NN)
#define NOUT 20
#define TAU  0.6f
#define KC   320            // Eigen kc panel size
#define NSEG 7              // ceil(2068/320)
#define MROWS (B_ * T_)     // 25600

#define CH   10             // timesteps per chunk
#define NCH  (T_ / CH)      // 10 chunks
#define RPC  (B_ * CH)      // 2560 rows per chunk

// ---------------- scratch (device globals; no runtime allocation) ----------
__device__ float g_ff[(size_t)MROWS * NNP];      // folded ff = (p0+p1)+p2
__device__ float g_xp[(size_t)MROWS * KP];       // x staged: [r = t*B+b][k], zero-padded
__device__ float g_w1t[(size_t)KP * NNP];        // W_fc1^T zero-padded: [k][n]
__device__ float g_mem[(size_t)B_ * NNP];        // inter-chunk membrane state
__device__ float g_spk[(size_t)B_ * NNP];        // inter-chunk spike state

// ---------------- streams/events (created once at load; no device memory) ---
struct GpuCtx {
    cudaStream_t sG;            // low priority: GEMM
    cudaStream_t sS;            // high priority: steps
    cudaEvent_t  evStage;
    cudaEvent_t  evG[NCH];
    cudaEvent_t  evJoin;
    GpuCtx() {
        int lo, hi;
        cudaDeviceGetStreamPriorityRange(&lo, &hi);
        cudaStreamCreateWithPriority(&sG, cudaStreamNonBlocking, lo);
        cudaStreamCreateWithPriority(&sS, cudaStreamNonBlocking, hi);
        cudaEventCreateWithFlags(&evStage, cudaEventDisableTiming);
        for (int i = 0; i < NCH; i++)
            cudaEventCreateWithFlags(&evG[i], cudaEventDisableTiming);
        cudaEventCreateWithFlags(&evJoin, cudaEventDisableTiming);
    }
};
static GpuCtx g_ctx;

// ---------------- staging ---------------------------------------------------
__global__ void pad_x_kernel(const float* __restrict__ x) {
    size_t idx = (size_t)blockIdx.x * blockDim.x + threadIdx.x;
    if (idx < (size_t)MROWS * KP) {
        int r = (int)(idx / KP);
        int k = (int)(idx - (size_t)r * KP);
        int t = r >> 8;                 // r = t*256 + b
        int b = r & 255;
        g_xp[idx] = (k < NIN) ? x[((size_t)b * T_ + t) * NIN + k] : 0.0f;
    }
}

__global__ void pad_w1t_kernel(const float* __restrict__ W1) {
    size_t idx = (size_t)blockIdx.x * blockDim.x + threadIdx.x;
    if (idx < (size_t)KP * NNP) {
        int k = (int)(idx / NNP);
        int n = (int)(idx - (size_t)k * NNP);
        g_w1t[idx] = (k < NIN && n < NN) ? W1[(size_t)n * NIN + k] : 0.0f;
    }
}

// ---------------- phase 1: GEMM with in-kernel panel fold (R13, unchanged) ---
#define BM 128
#define BN 64
#define BK 16
#define NKT (KP / BK)       // 44 k-tiles; panel folds before tiles 20 and 40

__global__ __launch_bounds__(256, 2) void gemm_fold_kernel(int row_off) {
    __shared__ float As[2][BK][BM];
    __shared__ float Bs[2][BK][BN];

    int tid  = threadIdx.x;
    int row0 = row_off + blockIdx.y * BM;
    int col0 = blockIdx.x * BN;

    int arow = tid >> 1;
    int asub = (tid & 1) * 8;
    const float* ap = g_xp + (size_t)(row0 + arow) * KP + asub;

    int bk  = tid >> 4;
    int bn4 = (tid & 15) * 4;
    const float* bp = g_w1t + (size_t)bk * NNP + (col0 + bn4);

    int tr = (tid >> 4) * 8;
    int tc = (tid & 15) * 4;

    float4 ra0, ra1, rb;

    ra0 = *(const float4*)(ap);
    ra1 = *(const float4*)(ap + 4);
    rb  = *(const float4*)(bp);

    As[0][asub + 0][arow] = ra0.x; As[0][asub + 1][arow] = ra0.y;
    As[0][asub + 2][arow] = ra0.z; As[0][asub + 3][arow] = ra0.w;
    As[0][asub + 4][arow] = ra1.x; As[0][asub + 5][arow] = ra1.y;
    As[0][asub + 6][arow] = ra1.z; As[0][asub + 7][arow] = ra1.w;
    *(float4*)&Bs[0][bk][bn4] = rb;
    __syncthreads();

    float tot[8][4], pac[8][4];
    #pragma unroll
    for (int i = 0; i < 8; i++)
        #pragma unroll
        for (int j = 0; j < 4; j++) { tot[i][j] = 0.0f; pac[i][j] = 0.0f; }

    for (int tI = 0; tI < NKT; tI++) {
        if (tI == 20 || tI == 40) {                 // panel boundary fold
            #pragma unroll
            for (int i = 0; i < 8; i++)
                #pragma unroll
                for (int j = 0; j < 4; j++) {
                    tot[i][j] = __fadd_rn(tot[i][j], pac[i][j]);
                    pac[i][j] = 0.0f;
                }
        }

        int  buf  = tI & 1;
        bool more = (tI + 1 < NKT);

        if (more) {
            const float* apn = ap + (tI + 1) * BK;
            ra0 = *(const float4*)(apn);
            ra1 = *(const float4*)(apn + 4);
            rb  = *(const float4*)(bp + (size_t)(tI + 1) * BK * NNP);
        }

        #pragma unroll
        for (int kk = 0; kk < BK; kk++) {
            float a[8], bv[4];
            *(float4*)&a[0]  = *(const float4*)&As[buf][kk][tr];
            *(float4*)&a[4]  = *(const float4*)&As[buf][kk][tr + 4];
            *(float4*)&bv[0] = *(const float4*)&Bs[buf][kk][tc];
            #pragma unroll
            for (int i = 0; i < 8; i++)
                #pragma unroll
                for (int j = 0; j < 4; j++)
                    pac[i][j] = __fmaf_rn(a[i], bv[j], pac[i][j]);
        }

        if (more) {
            int nb = buf ^ 1;
            As[nb][asub + 0][arow] = ra0.x; As[nb][asub + 1][arow] = ra0.y;
            As[nb][asub + 2][arow] = ra0.z; As[nb][asub + 3][arow] = ra0.w;
            As[nb][asub + 4][arow] = ra1.x; As[nb][asub + 5][arow] = ra1.y;
            As[nb][asub + 6][arow] = ra1.z; As[nb][asub + 7][arow] = ra1.w;
            *(float4*)&Bs[nb][bk][bn4] = rb;
        }
        __syncthreads();
    }

    #pragma unroll
    for (int i = 0; i < 8; i++) {
        #pragma unroll
        for (int j = 0; j < 4; j++)
            tot[i][j] = __fadd_rn(tot[i][j], pac[i][j]);   // final panel fold
        *(float4*)(g_ff + (size_t)(row0 + tr + i) * NNP + (col0 + tc)) = *(float4*)&tot[i][0];
    }
}

// ---------------- phase 2: CH-step LIF, pure-float4 lanes --------------------
// 512 threads: thread tid owns f4 column tid (n = 4tid..4tid+3). Warp 0 lanes
// 0..4 additionally own f4 columns 512..516 (n = 2048..2067 = outputs).
#define NT    512
#define W4ROW 517            // 2068/4 float4s per W_rec row (exact)

__device__ __forceinline__ float4 f4add(float4 a, float4 b) {
    return make_float4(__fadd_rn(a.x, b.x), __fadd_rn(a.y, b.y),
                       __fadd_rn(a.z, b.z), __fadd_rn(a.w, b.w));
}
__device__ __forceinline__ float4 f4zero() { return make_float4(0.f, 0.f, 0.f, 0.f); }

__global__ __launch_bounds__(NT, 2) void steps_kernel(const float* __restrict__ Wrec,
                                                      float* __restrict__ out, int t0) {
    __shared__ int s_list[NN];
    __shared__ int s_wcnt[16];
    __shared__ int s_tcnt;
    __shared__ int s_seg[NSEG];

    int b    = blockIdx.x;
    int tid  = threadIdx.x;
    int wid  = tid >> 5;
    int lane = tid & 31;
    bool w0  = (wid == 0);
    bool tl  = w0 && (lane < 5);       // tail lane

    const float4* W4 = (const float4*)Wrec;
    size_t sb4 = ((size_t)b * NNP) >> 2;   // f4 index of state row

    float4 mv, sv, mvt, svt;
    if (t0 == 0) {
        mv = f4zero(); sv = f4zero(); mvt = f4zero(); svt = f4zero();
    } else {
        mv  = ((const float4*)g_mem)[sb4 + tid];
        sv  = ((const float4*)g_spk)[sb4 + tid];
        mvt = tl ? ((const float4*)g_mem)[sb4 + 512 + lane] : f4zero();
        svt = tl ? ((const float4*)g_spk)[sb4 + 512 + lane] : f4zero();
    }

    for (int t = t0; t < t0 + CH; t++) {
        // ---- ff load (already panel-folded by GEMM) ----
        size_t rb4 = (((size_t)t * B_ + b) * NNP) >> 2;
        float4 ffv = ((const float4*)g_ff)[rb4 + tid];
        float4 fft = tl ? ((const float4*)g_ff)[rb4 + 512 + lane] : f4zero();

        // ---- compaction: 4-bit masks + warp scan + cross-warp prefix ----
        unsigned am = (sv.x != 0.f ? 1u : 0u) | (sv.y != 0.f ? 2u : 0u)
                    | (sv.z != 0.f ? 4u : 0u) | (sv.w != 0.f ? 8u : 0u);
        int nact = __popc(am);
        int scan = nact;
        #pragma unroll
        for (int d = 1; d < 32; d <<= 1) {
            int o = __shfl_up_sync(0xffffffffu, scan, d);
            if (lane >= d) scan += o;
        }
        if (lane == 31) s_wcnt[wid] = scan;
        __syncthreads();

        int vbase = 0, vtotal = 0;
        #pragma unroll
        for (int w = 0; w < 16; w++) {
            int c = s_wcnt[w];
            if (w < wid) vbase += c;
            vtotal += c;
        }
        int pos = vbase + (scan - nact);
        if (am & 1u) s_list[pos++] = 4 * tid + 0;
        if (am & 2u) s_list[pos++] = 4 * tid + 1;
        if (am & 4u) s_list[pos++] = 4 * tid + 2;
        if (am & 8u) s_list[pos++] = 4 * tid + 3;

        // tail compaction (warp 0 only; lanes >=5 contribute empty masks)
        if (w0) {
            unsigned tam = 0;
            if (tl)
                tam = (svt.x != 0.f ? 1u : 0u) | (svt.y != 0.f ? 2u : 0u)
                    | (svt.z != 0.f ? 4u : 0u) | (svt.w != 0.f ? 8u : 0u);
            int tn = __popc(tam);
            int tscan = tn;
            #pragma unroll
            for (int d = 1; d < 32; d <<= 1) {
                int o = __shfl_up_sync(0xffffffffu, tscan, d);
                if (lane >= d) tscan += o;
            }
            if (lane == 31) s_tcnt = tscan;
            int tpos = vtotal + (tscan - tn);
            if (tam & 1u) s_list[tpos++] = 2048 + 4 * lane + 0;
            if (tam & 2u) s_list[tpos++] = 2048 + 4 * lane + 1;
            if (tam & 4u) s_list[tpos++] = 2048 + 4 * lane + 2;
            if (tam & 8u) s_list[tpos++] = 2048 + 4 * lane + 3;
        }
        __syncthreads();

        int cnt = vtotal + s_tcnt;

        // ---- segment boundaries: lower_bound of (p+1)*320 in s_list ----
        if (tid < NSEG) {
            int target = (tid + 1) * KC;
            int lo = 0, hi = cnt;
            while (lo < hi) {
                int mid = (lo + hi) >> 1;
                if (s_list[mid] < target) lo = mid + 1; else hi = mid;
            }
            s_seg[tid] = lo;
        }
        __syncthreads();

        // ---- rec: per-segment plain adds, fold between segments ----
        float4 rec  = f4zero();
        float4 rect = f4zero();

        int start = 0;
        #pragma unroll 1
        for (int p = 0; p < NSEG; p++) {
            int end = s_seg[p];
            float4 part  = f4zero();
            float4 partt = f4zero();
            int i = start;
            for (; i + 4 <= end; i += 4) {
                int m0 = s_list[i + 0], m1 = s_list[i + 1];
                int m2 = s_list[i + 2], m3 = s_list[i + 3];
                float4 v0 = W4[(size_t)m0 * W4ROW + tid];
                float4 v1 = W4[(size_t)m1 * W4ROW + tid];
                float4 v2 = W4[(size_t)m2 * W4ROW + tid];
                float4 v3 = W4[(size_t)m3 * W4ROW + tid];
                if (w0) {                                   // warp-uniform branch
                    float4 u0 = tl ? W4[(size_t)m0 * W4ROW + 512 + lane] : f4zero();
                    float4 u1 = tl ? W4[(size_t)m1 * W4ROW + 512 + lane] : f4zero();
                    float4 u2 = tl ? W4[(size_t)m2 * W4ROW + 512 + lane] : f4zero();
                    float4 u3 = tl ? W4[(size_t)m3 * W4ROW + 512 + lane] : f4zero();
                    partt = f4add(partt, u0);
                    partt = f4add(partt, u1);
                    partt = f4add(partt, u2);
                    partt = f4add(partt, u3);
                }
                part = f4add(part, v0);
                part = f4add(part, v1);
                part = f4add(part, v2);
                part = f4add(part, v3);
            }
            for (; i < end; i++) {
                int mr = s_list[i];
                float4 v0 = W4[(size_t)mr * W4ROW + tid];
                if (w0) {
                    float4 u0 = tl ? W4[(size_t)mr * W4ROW + 512 + lane] : f4zero();
                    partt = f4add(partt, u0);
                }
                part = f4add(part, v0);
            }
            rec = f4add(rec, part);                  // fadd(x,+0) == x empty segs
            if (w0) rect = f4add(rect, partt);
            start = end;
        }

        // ---- membrane update + spikes (unfused, reference order) ----
        {
            float4 cur = f4add(ffv, rec);
            mv = make_float4(
                __fadd_rn(__fmul_rn(__fmul_rn(TAU, mv.x), __fsub_rn(1.f, sv.x)), cur.x),
                __fadd_rn(__fmul_rn(__fmul_rn(TAU, mv.y), __fsub_rn(1.f, sv.y)), cur.y),
                __fadd_rn(__fmul_rn(__fmul_rn(TAU, mv.z), __fsub_rn(1.f, sv.z)), cur.z),
                __fadd_rn(__fmul_rn(__fmul_rn(TAU, mv.w), __fsub_rn(1.f, sv.w)), cur.w));
            sv = make_float4(mv.x >= 1.f ? 1.f : 0.f, mv.y >= 1.f ? 1.f : 0.f,
                             mv.z >= 1.f ? 1.f : 0.f, mv.w >= 1.f ? 1.f : 0.f);
        }
        if (tl) {
            float4 cur = f4add(fft, rect);
            mvt = make_float4(
                __fadd_rn(__fmul_rn(__fmul_rn(TAU, mvt.x), __fsub_rn(1.f, svt.x)), cur.x),
                __fadd_rn(__fmul_rn(__fmul_rn(TAU, mvt.y), __fsub_rn(1.f, svt.y)), cur.y),
                __fadd_rn(__fmul_rn(__fmul_rn(TAU, mvt.z), __fsub_rn(1.f, svt.z)), cur.z),
                __fadd_rn(__fmul_rn(__fmul_rn(TAU, mvt.w), __fsub_rn(1.f, svt.w)), cur.w));
            svt = make_float4(mvt.x >= 1.f ? 1.f : 0.f, mvt.y >= 1.f ? 1.f : 0.f,
                              mvt.z >= 1.f ? 1.f : 0.f, mvt.w >= 1.f ? 1.f : 0.f);
            *(float4*)(out + ((size_t)b * T_ + t) * NOUT + 4 * lane) = svt;
        }

        __syncthreads();   // protect s_list/s_wcnt/s_seg reuse next step
    }

    // ---- park state for next chunk ----
    ((float4*)g_mem)[sb4 + tid] = mv;
    ((float4*)g_spk)[sb4 + tid] = sv;
    if (tl) {
        ((float4*)g_mem)[sb4 + 512 + lane] = mvt;
        ((float4*)g_spk)[sb4 + 512 + lane] = svt;
    }
}

// ---------------- launch: prioritized stream-forked chunk pipeline -----------
extern "C" void kernel_launch(void* const* d_in, const int* in_sizes, int n_in,
                              void* d_out, int out_size) {
    const float* x  = (const float*)d_in[0];   // [B, T, NIN]
    const float* W1 = (const float*)d_in[1];   // [NN, NIN]
    const float* Wr = (const float*)d_in[2];   // [NN, NN]
    float* out = (float*)d_out;                // [B, T, NOUT]

    // staging on origin stream
    {
        size_t n = (size_t)MROWS * KP;
        pad_x_kernel<<<(unsigned)((n + 255) / 256), 256>>>(x);
    }
    {
        size_t n = (size_t)KP * NNP;
        pad_w1t_kernel<<<(unsigned)((n + 255) / 256), 256>>>(W1);
    }
    cudaEventRecord(g_ctx.evStage, 0);

    // GEMM chunks on low-priority stream sG
    cudaStreamWaitEvent(g_ctx.sG, g_ctx.evStage, 0);
    dim3 ggrid(NCOLB, RPC / BM);               // 33 x 20 per chunk
    for (int c = 0; c < NCH; c++) {
        gemm_fold_kernel<<<ggrid, 256, 0, g_ctx.sG>>>(c * RPC);
        cudaEventRecord(g_ctx.evG[c], g_ctx.sG);
    }

    // steps chunks on high-priority stream sS, each gated on its GEMM chunk
    for (int c = 0; c < NCH; c++) {
        cudaStreamWaitEvent(g_ctx.sS, g_ctx.evG[c], 0);
        steps_kernel<<<B_, NT, 0, g_ctx.sS>>>(Wr, out, c * CH);
    }

    // join forked work back to the origin stream (graph-capture requirement)
    cudaEventRecord(g_ctx.evJoin, g_ctx.sS);
    cudaStreamWaitEvent(0, g_ctx.evJoin, 0);
}